// round 1
// baseline (speedup 1.0000x reference)
#include <cuda_runtime.h>
#include <cstdint>

// temporal_attention: x [B=2, T=8192, D=64] f32
//   S = X X^T ; y = softmax(S, dim=1)  (column-normalized: over i for fixed j)
//   out = (y @ X) transposed -> [B, D, T]
//
// Strategy (two-pass, shift = ||x_j||^2 so no max pass needed):
//   k_norm : a_j = ||x_j||^2                       (fp32)
//   k_stats: r_j = 1 / sum_i exp(s_ij - a_j)        (tf32 mma scores)
//   k_out  : out_i = sum_j exp(s_ij - a_j) * r_j * x_j   (tf32 mma, P via SMEM)
// All score GEMMs use identically tf32-rounded inputs so pass1/pass2 weights
// are consistent (softmax self-normalization then cancels rounding on the
// dominant diagonal weights).

#define T_DIM 8192
#define D_DIM 64
#define B_DIM 2
#define LDA   68      // padded stride for 128x64 x-tiles (conflict-free for gid*68+tg)
#define LDP   132     // padded stride for 128x128 P tile

__device__ float g_a[B_DIM * T_DIM];
__device__ float g_r[B_DIM * T_DIM];

__device__ __forceinline__ unsigned f2tf32(float x) {
    unsigned u;
    asm("cvt.rna.tf32.f32 %0, %1;" : "=r"(u) : "f"(x));
    return u;
}

__device__ __forceinline__ void mma_tf32(float* c, const unsigned* a, const unsigned* b) {
    asm volatile(
        "mma.sync.aligned.m16n8k8.row.col.f32.tf32.tf32.f32 "
        "{%0,%1,%2,%3}, {%4,%5,%6,%7}, {%8,%9}, {%0,%1,%2,%3};"
        : "+f"(c[0]), "+f"(c[1]), "+f"(c[2]), "+f"(c[3])
        : "r"(a[0]), "r"(a[1]), "r"(a[2]), "r"(a[3]),
          "r"(b[0]), "r"(b[1]));
}

// ---------------------------------------------------------------------------
// k_norm: a_j = sum_d x[j][d]^2 (fp32, raw x)
// ---------------------------------------------------------------------------
__global__ void k_norm(const float* __restrict__ x) {
    int j = blockIdx.x * blockDim.x + threadIdx.x;  // 0 .. B*T-1
    const float* p = x + (size_t)j * D_DIM;
    float s = 0.f;
#pragma unroll
    for (int d = 0; d < D_DIM; d++) s += p[d] * p[d];
    g_a[j] = s;
}

// ---------------------------------------------------------------------------
// k_stats: per j-tile of 128 columns, accumulate c_j = sum_i exp(s_ij - a_j)
// Computes tiles C[j_local, i_local] = Xj * Xi^T so the reduction over i is a
// row reduction (in-register accumulation across the whole i loop).
// ---------------------------------------------------------------------------
__global__ void __launch_bounds__(256, 1) k_stats(const float* __restrict__ x) {
    extern __shared__ float sm[];
    float* sA  = sm;                 // Xj tile  128 x LDA
    float* sB  = sm + 128 * LDA;     // Xi tile  128 x LDA
    float* red = sm + 2 * 128 * LDA; // 4 x 128

    const int b  = blockIdx.y;
    const int j0 = blockIdx.x * 128;
    const float* xb = x + (size_t)b * T_DIM * D_DIM;

    const int tid  = threadIdx.x;
    const int lane = tid & 31;
    const int w    = tid >> 5;
    const int wm = w >> 2, wn = w & 3;
    const int gid = lane >> 2, tg = lane & 3;

    // load Xj tile (tf32-rounded)
#pragma unroll
    for (int k = 0; k < 32; k++) {
        int i = tid + k * 256;
        int r = i >> 6, c = i & 63;
        sA[r * LDA + c] = __uint_as_float(f2tf32(xb[(size_t)(j0 + r) * D_DIM + c]));
    }

    // per-thread row shifts a_j (rows of this tile owned by this thread)
    float a_r[4][2];
#pragma unroll
    for (int mf = 0; mf < 4; mf++) {
        int r = wm * 64 + mf * 16 + gid;
        a_r[mf][0] = g_a[b * T_DIM + j0 + r];
        a_r[mf][1] = g_a[b * T_DIM + j0 + r + 8];
    }

    float rs[4][2];
#pragma unroll
    for (int mf = 0; mf < 4; mf++) { rs[mf][0] = 0.f; rs[mf][1] = 0.f; }

    for (int it = 0; it < T_DIM / 128; it++) {
        __syncthreads();  // previous GEMM done reading sB
#pragma unroll
        for (int k = 0; k < 32; k++) {
            int i = tid + k * 256;
            int r = i >> 6, c = i & 63;
            sB[r * LDA + c] = __uint_as_float(f2tf32(xb[(size_t)(it * 128 + r) * D_DIM + c]));
        }
        __syncthreads();

        float acc[4][4][4];
#pragma unroll
        for (int mf = 0; mf < 4; mf++)
#pragma unroll
            for (int nf = 0; nf < 4; nf++)
#pragma unroll
                for (int q = 0; q < 4; q++) acc[mf][nf][q] = 0.f;

#pragma unroll
        for (int kk = 0; kk < 8; kk++) {
            const int k0 = kk * 8;
            unsigned A[4][4], Bf[4][2];
#pragma unroll
            for (int mf = 0; mf < 4; mf++) {
                int r = wm * 64 + mf * 16 + gid;
                A[mf][0] = __float_as_uint(sA[r * LDA + k0 + tg]);
                A[mf][1] = __float_as_uint(sA[(r + 8) * LDA + k0 + tg]);
                A[mf][2] = __float_as_uint(sA[r * LDA + k0 + tg + 4]);
                A[mf][3] = __float_as_uint(sA[(r + 8) * LDA + k0 + tg + 4]);
            }
#pragma unroll
            for (int nf = 0; nf < 4; nf++) {
                int cB = wn * 32 + nf * 8 + gid;
                Bf[nf][0] = __float_as_uint(sB[cB * LDA + k0 + tg]);
                Bf[nf][1] = __float_as_uint(sB[cB * LDA + k0 + tg + 4]);
            }
#pragma unroll
            for (int mf = 0; mf < 4; mf++)
#pragma unroll
                for (int nf = 0; nf < 4; nf++)
                    mma_tf32(acc[mf][nf], A[mf], Bf[nf]);
        }

        // accumulate row sums of exp(s - a_row)
#pragma unroll
        for (int mf = 0; mf < 4; mf++)
#pragma unroll
            for (int nf = 0; nf < 4; nf++) {
                rs[mf][0] += __expf(acc[mf][nf][0] - a_r[mf][0])
                           + __expf(acc[mf][nf][1] - a_r[mf][0]);
                rs[mf][1] += __expf(acc[mf][nf][2] - a_r[mf][1])
                           + __expf(acc[mf][nf][3] - a_r[mf][1]);
            }
    }

    // reduce across the quad (columns within warp), then across the 4 n-warps
#pragma unroll
    for (int mf = 0; mf < 4; mf++)
#pragma unroll
        for (int h = 0; h < 2; h++) {
            float v = rs[mf][h];
            v += __shfl_xor_sync(0xFFFFFFFFu, v, 1);
            v += __shfl_xor_sync(0xFFFFFFFFu, v, 2);
            rs[mf][h] = v;
        }
    __syncthreads();
    if (tg == 0) {
#pragma unroll
        for (int mf = 0; mf < 4; mf++) {
            int r = wm * 64 + mf * 16 + gid;
            red[wn * 128 + r]     = rs[mf][0];
            red[wn * 128 + r + 8] = rs[mf][1];
        }
    }
    __syncthreads();
    if (tid < 128) {
        float c = red[tid] + red[128 + tid] + red[256 + tid] + red[384 + tid];
        g_r[b * T_DIM + j0 + tid] = 1.0f / c;
    }
}

// ---------------------------------------------------------------------------
// k_out: per i-tile of 128 rows, out_i = sum_j exp(s_ij - a_j) r_j x_j,
// written transposed: out[b][d][i].
// ---------------------------------------------------------------------------
__global__ void __launch_bounds__(256, 1) k_out(const float* __restrict__ x,
                                                float* __restrict__ out) {
    extern __shared__ float sm[];
    float* sXi = sm;                       // 128 x LDA
    float* sXj = sm + 128 * LDA;           // 128 x LDA
    float* sP  = sm + 2 * 128 * LDA;       // 128 x LDP
    float* sa  = sP + 128 * LDP;           // 128
    float* sr  = sa + 128;                 // 128

    const int b  = blockIdx.y;
    const int i0 = blockIdx.x * 128;
    const float* xb = x + (size_t)b * T_DIM * D_DIM;
    float* ob = out + (size_t)b * D_DIM * T_DIM;

    const int tid  = threadIdx.x;
    const int lane = tid & 31;
    const int w    = tid >> 5;
    const int wm = w >> 2, wn = w & 3;
    const int gid = lane >> 2, tg = lane & 3;

#pragma unroll
    for (int k = 0; k < 32; k++) {
        int i = tid + k * 256;
        int r = i >> 6, c = i & 63;
        sXi[r * LDA + c] = __uint_as_float(f2tf32(xb[(size_t)(i0 + r) * D_DIM + c]));
    }

    float accO[4][2][4];
#pragma unroll
    for (int mf = 0; mf < 4; mf++)
#pragma unroll
        for (int nf = 0; nf < 2; nf++)
#pragma unroll
            for (int q = 0; q < 4; q++) accO[mf][nf][q] = 0.f;

    for (int jt = 0; jt < T_DIM / 128; jt++) {
        __syncthreads();  // previous PV done reading sXj / sP
#pragma unroll
        for (int k = 0; k < 32; k++) {
            int i = tid + k * 256;
            int r = i >> 6, c = i & 63;
            sXj[r * LDA + c] = __uint_as_float(f2tf32(xb[(size_t)(jt * 128 + r) * D_DIM + c]));
        }
        if (tid < 128) {
            sa[tid] = g_a[b * T_DIM + jt * 128 + tid];
            sr[tid] = g_r[b * T_DIM + jt * 128 + tid];
        }
        __syncthreads();

        // ---- S = Xi * Xj^T (128x128) ----
        float accS[4][4][4];
#pragma unroll
        for (int mf = 0; mf < 4; mf++)
#pragma unroll
            for (int nf = 0; nf < 4; nf++)
#pragma unroll
                for (int q = 0; q < 4; q++) accS[mf][nf][q] = 0.f;

#pragma unroll
        for (int kk = 0; kk < 8; kk++) {
            const int k0 = kk * 8;
            unsigned A[4][4], Bf[4][2];
#pragma unroll
            for (int mf = 0; mf < 4; mf++) {
                int r = wm * 64 + mf * 16 + gid;
                A[mf][0] = __float_as_uint(sXi[r * LDA + k0 + tg]);
                A[mf][1] = __float_as_uint(sXi[(r + 8) * LDA + k0 + tg]);
                A[mf][2] = __float_as_uint(sXi[r * LDA + k0 + tg + 4]);
                A[mf][3] = __float_as_uint(sXi[(r + 8) * LDA + k0 + tg + 4]);
            }
#pragma unroll
            for (int nf = 0; nf < 4; nf++) {
                int cB = wn * 32 + nf * 8 + gid;
                Bf[nf][0] = __float_as_uint(sXj[cB * LDA + k0 + tg]);
                Bf[nf][1] = __float_as_uint(sXj[cB * LDA + k0 + tg + 4]);
            }
#pragma unroll
            for (int mf = 0; mf < 4; mf++)
#pragma unroll
                for (int nf = 0; nf < 4; nf++)
                    mma_tf32(accS[mf][nf], A[mf], Bf[nf]);
        }

        // ---- P = exp(S - a_j) * r_j  ->  SMEM (tf32-rounded) ----
#pragma unroll
        for (int nf = 0; nf < 4; nf++) {
            int c0 = wn * 32 + nf * 8 + 2 * tg;
            float a0 = sa[c0], a1 = sa[c0 + 1];
            float r0 = sr[c0], r1 = sr[c0 + 1];
#pragma unroll
            for (int mf = 0; mf < 4; mf++) {
                int r = wm * 64 + mf * 16 + gid;
                float p0 = __expf(accS[mf][nf][0] - a0) * r0;
                float p1 = __expf(accS[mf][nf][1] - a1) * r1;
                float p2 = __expf(accS[mf][nf][2] - a0) * r0;
                float p3 = __expf(accS[mf][nf][3] - a1) * r1;
                sP[r * LDP + c0]           = __uint_as_float(f2tf32(p0));
                sP[r * LDP + c0 + 1]       = __uint_as_float(f2tf32(p1));
                sP[(r + 8) * LDP + c0]     = __uint_as_float(f2tf32(p2));
                sP[(r + 8) * LDP + c0 + 1] = __uint_as_float(f2tf32(p3));
            }
        }
        __syncthreads();

        // ---- O += P (128x128) * Xj (128x64) ----
#pragma unroll
        for (int kk = 0; kk < 16; kk++) {
            const int k0 = kk * 8;
            unsigned A[4][4], Bf[2][2];
#pragma unroll
            for (int mf = 0; mf < 4; mf++) {
                int r = wm * 64 + mf * 16 + gid;
                A[mf][0] = __float_as_uint(sP[r * LDP + k0 + tg]);
                A[mf][1] = __float_as_uint(sP[(r + 8) * LDP + k0 + tg]);
                A[mf][2] = __float_as_uint(sP[r * LDP + k0 + tg + 4]);
                A[mf][3] = __float_as_uint(sP[(r + 8) * LDP + k0 + tg + 4]);
            }
#pragma unroll
            for (int nf = 0; nf < 2; nf++) {
                int cB = wn * 16 + nf * 8 + gid;
                Bf[nf][0] = __float_as_uint(sXj[(k0 + tg) * LDA + cB]);
                Bf[nf][1] = __float_as_uint(sXj[(k0 + tg + 4) * LDA + cB]);
            }
#pragma unroll
            for (int mf = 0; mf < 4; mf++)
#pragma unroll
                for (int nf = 0; nf < 2; nf++)
                    mma_tf32(accO[mf][nf], A[mf], Bf[nf]);
        }
    }

    // ---- store transposed: out[b][d][i] ----
#pragma unroll
    for (int mf = 0; mf < 4; mf++)
#pragma unroll
        for (int nf = 0; nf < 2; nf++) {
            int r = i0 + wm * 64 + mf * 16 + gid;
            int c = wn * 16 + nf * 8 + 2 * tg;
            ob[(size_t)c * T_DIM + r]           = accO[mf][nf][0];
            ob[(size_t)(c + 1) * T_DIM + r]     = accO[mf][nf][1];
            ob[(size_t)c * T_DIM + r + 8]       = accO[mf][nf][2];
            ob[(size_t)(c + 1) * T_DIM + r + 8] = accO[mf][nf][3];
        }
}

// ---------------------------------------------------------------------------

extern "C" void kernel_launch(void* const* d_in, const int* in_sizes, int n_in,
                              void* d_out, int out_size) {
    const float* x = (const float*)d_in[0];
    float* out = (float*)d_out;

    const int smem_stats = (2 * 128 * LDA + 4 * 128) * sizeof(float);           // 71,680
    const int smem_out   = (2 * 128 * LDA + 128 * LDP + 256) * sizeof(float);   // 138,240

    cudaFuncSetAttribute(k_stats, cudaFuncAttributeMaxDynamicSharedMemorySize, smem_stats);
    cudaFuncSetAttribute(k_out,   cudaFuncAttributeMaxDynamicSharedMemorySize, smem_out);

    k_norm<<<(B_DIM * T_DIM) / 256, 256>>>(x);
    k_stats<<<dim3(T_DIM / 128, B_DIM), 256, smem_stats>>>(x);
    k_out<<<dim3(T_DIM / 128, B_DIM), 256, smem_out>>>(x, out);
}

// round 3
// speedup vs baseline: 1.8146x; 1.8146x over previous
#include <cuda_runtime.h>
#include <cuda_fp16.h>
#include <cstdint>

// temporal_attention: x [B=2, T=8192, D=64] f32
//   S = X X^T ; y = softmax(S, dim=1) (column-normalized); out = (y @ X)^T
// Two-pass, shift a_j = ||x_j||^2 (no max pass). Legacy mma.sync fp16 path
// (tcgen05 unavailable: harness PTX targets sm_103 without the 'a' feature set).
//   k_prep : a_j (fp32) + g_xh = half(x)
//   k_xt   : g_xth[b][d][t] = half(x[b][t][d])
//   k_stats: r_j = 1/sum_i exp(s_ij - a_j)        (fp16 mma, fp32 acc)
//   k_out  : out_i = sum_j exp(s_ij - a_j) r_j x_j (fp16 mma, P as fp16)

#define T_DIM 8192
#define D_DIM 64
#define B_DIM 2
#define NCH   128
#define NIT   (T_DIM / NCH)   // 64
#define LDX   72              // half stride for [128|64 x 64] x-tiles
#define LDT   136             // half stride for [64 x 128] xT tile and [128 x 128] P tile

__device__ float  g_a[B_DIM * T_DIM];
__device__ float  g_r[B_DIM * T_DIM];
__device__ __half g_xh[B_DIM * T_DIM * D_DIM];
__device__ __half g_xth[B_DIM * D_DIM * T_DIM];

// ---------------- helpers ----------------
__device__ __forceinline__ uint32_t smem_u32(const void* p) {
    uint32_t a;
    asm("{ .reg .u64 t; cvta.to.shared.u64 t, %1; cvt.u32.u64 %0, t; }" : "=r"(a) : "l"(p));
    return a;
}
__device__ __forceinline__ void cpa16(uint32_t s, const void* g) {
    asm volatile("cp.async.cg.shared.global [%0], [%1], 16;" :: "r"(s), "l"(g));
}
#define CP_COMMIT() asm volatile("cp.async.commit_group;" ::: "memory")
#define CP_WAIT0()  asm volatile("cp.async.wait_group 0;" ::: "memory")

__device__ __forceinline__ void mma_f16(float* c, const uint32_t* a, const uint32_t* b) {
    asm volatile(
        "mma.sync.aligned.m16n8k16.row.col.f32.f16.f16.f32 "
        "{%0,%1,%2,%3}, {%4,%5,%6,%7}, {%8,%9}, {%0,%1,%2,%3};"
        : "+f"(c[0]), "+f"(c[1]), "+f"(c[2]), "+f"(c[3])
        : "r"(a[0]), "r"(a[1]), "r"(a[2]), "r"(a[3]), "r"(b[0]), "r"(b[1]));
}

// load [128 x 64] half tile (row stride LDX) from g (row stride 64) via cp.async
__device__ __forceinline__ void ld_x(uint32_t dst, const __half* g, int tid) {
#pragma unroll
    for (int p = 0; p < 4; p++) {
        int e = p * 2048 + tid * 8;
        int r = e >> 6, c = e & 63;
        cpa16(dst + (uint32_t)(r * (LDX * 2) + c * 2), g + (size_t)r * D_DIM + c);
    }
}
// load [64 x 128] half tile (row stride LDT) from gt (row stride T_DIM) via cp.async
__device__ __forceinline__ void ld_xt(uint32_t dst, const __half* gt, int tid) {
#pragma unroll
    for (int p = 0; p < 4; p++) {
        int e = p * 2048 + tid * 8;
        int d = e >> 7, j = e & 127;
        cpa16(dst + (uint32_t)(d * (LDT * 2) + j * 2), gt + (size_t)d * T_DIM + j);
    }
}

// ---------------- k_prep: a_j + half conversion ----------------
__global__ void k_prep(const float* __restrict__ x) {
    const int tid = threadIdx.x;
    const int j = blockIdx.x * 16 + (tid >> 4);   // 16 rows per block
    const int l = tid & 15;                       // 16 lanes per row
    const float4 v = *reinterpret_cast<const float4*>(x + (size_t)j * D_DIM + l * 4);
    float s = v.x * v.x + v.y * v.y + v.z * v.z + v.w * v.w;
    s += __shfl_xor_sync(0xFFFFFFFFu, s, 8);
    s += __shfl_xor_sync(0xFFFFFFFFu, s, 4);
    s += __shfl_xor_sync(0xFFFFFFFFu, s, 2);
    s += __shfl_xor_sync(0xFFFFFFFFu, s, 1);
    if (l == 0) g_a[j] = s;
    __half2 h0 = __floats2half2_rn(v.x, v.y);
    __half2 h1 = __floats2half2_rn(v.z, v.w);
    uint2 pk;
    pk.x = *reinterpret_cast<uint32_t*>(&h0);
    pk.y = *reinterpret_cast<uint32_t*>(&h1);
    *reinterpret_cast<uint2*>(&g_xh[(size_t)j * D_DIM + l * 4]) = pk;
}

// ---------------- k_xt: g_xth[b][d][t] ----------------
__global__ void k_xt(const float* __restrict__ x) {
    __shared__ float tile[32][33];
    const int b = blockIdx.z, t0 = blockIdx.x * 32, d0 = blockIdx.y * 32;
    const int tx = threadIdx.x & 31, ty = threadIdx.x >> 5;
#pragma unroll
    for (int i = 0; i < 32; i += 8)
        tile[i + ty][tx] = x[((size_t)b * T_DIM + t0 + i + ty) * D_DIM + d0 + tx];
    __syncthreads();
#pragma unroll
    for (int i = 0; i < 32; i += 8)
        g_xth[((size_t)b * D_DIM + d0 + i + ty) * T_DIM + t0 + tx] =
            __float2half_rn(tile[tx][i + ty]);
}

// ---------------- k_stats ----------------
// smem: red[256 f32] @0 | sA @1024 | sB0 @19456 | sB1 @37888 | total 56320
__global__ void __launch_bounds__(256, 1) k_stats() {
    extern __shared__ char sm[];
    const uint32_t smb = smem_u32(sm);
    const int tid = threadIdx.x, w = tid >> 5, lane = tid & 31;
    const int wm = w >> 2, wn = w & 3;
    const int gid = lane >> 2, tg = lane & 3;
    const int b = blockIdx.y, j0 = blockIdx.x * 128;
    const __half* xh = g_xh + (size_t)b * T_DIM * D_DIM;

    const uint32_t SA = 1024, SB0 = 19456, SB1 = 37888;
    float* red = reinterpret_cast<float*>(sm);
    const __half* pA = reinterpret_cast<const __half*>(sm + SA);

    ld_x(smb + SA, xh + (size_t)j0 * D_DIM, tid);
    ld_x(smb + SB0, xh, tid);
    CP_COMMIT();
    CP_WAIT0();
    __syncthreads();

    float a_r[4][2];
#pragma unroll
    for (int mf = 0; mf < 4; mf++) {
        int r = wm * 64 + mf * 16 + gid;
        a_r[mf][0] = g_a[b * T_DIM + j0 + r];
        a_r[mf][1] = g_a[b * T_DIM + j0 + r + 8];
    }
    float rs[4][2];
#pragma unroll
    for (int mf = 0; mf < 4; mf++) { rs[mf][0] = 0.f; rs[mf][1] = 0.f; }

    for (int t = 0; t < NIT; t++) {
        const uint32_t SB = (t & 1) ? SB1 : SB0;
        const uint32_t SBn = (t & 1) ? SB0 : SB1;
        if (t + 1 < NIT) {
            ld_x(smb + SBn, xh + (size_t)(t + 1) * NCH * D_DIM, tid);
            CP_COMMIT();
        }
        const __half* pB = reinterpret_cast<const __half*>(sm + SB);

        float acc[4][4][4];
#pragma unroll
        for (int mf = 0; mf < 4; mf++)
#pragma unroll
            for (int nf = 0; nf < 4; nf++)
#pragma unroll
                for (int q = 0; q < 4; q++) acc[mf][nf][q] = 0.f;

#pragma unroll
        for (int kk = 0; kk < 4; kk++) {
            const int k0 = kk * 16;
            uint32_t A[4][4], Bf[4][2];
#pragma unroll
            for (int mf = 0; mf < 4; mf++) {
                int r = wm * 64 + mf * 16 + gid;
                A[mf][0] = *reinterpret_cast<const uint32_t*>(pA + r * LDX + k0 + 2 * tg);
                A[mf][1] = *reinterpret_cast<const uint32_t*>(pA + (r + 8) * LDX + k0 + 2 * tg);
                A[mf][2] = *reinterpret_cast<const uint32_t*>(pA + r * LDX + k0 + 8 + 2 * tg);
                A[mf][3] = *reinterpret_cast<const uint32_t*>(pA + (r + 8) * LDX + k0 + 8 + 2 * tg);
            }
#pragma unroll
            for (int nf = 0; nf < 4; nf++) {
                int cB = wn * 32 + nf * 8 + gid;
                Bf[nf][0] = *reinterpret_cast<const uint32_t*>(pB + cB * LDX + k0 + 2 * tg);
                Bf[nf][1] = *reinterpret_cast<const uint32_t*>(pB + cB * LDX + k0 + 8 + 2 * tg);
            }
#pragma unroll
            for (int mf = 0; mf < 4; mf++)
#pragma unroll
                for (int nf = 0; nf < 4; nf++)
                    mma_f16(acc[mf][nf], A[mf], Bf[nf]);
        }

#pragma unroll
        for (int mf = 0; mf < 4; mf++)
#pragma unroll
            for (int nf = 0; nf < 4; nf++) {
                rs[mf][0] += __expf(acc[mf][nf][0] - a_r[mf][0])
                           + __expf(acc[mf][nf][1] - a_r[mf][0]);
                rs[mf][1] += __expf(acc[mf][nf][2] - a_r[mf][1])
                           + __expf(acc[mf][nf][3] - a_r[mf][1]);
            }

        if (t + 1 < NIT) CP_WAIT0();
        __syncthreads();
    }

    // reduce over quad lanes (cols) then over the 4 n-warps
#pragma unroll
    for (int mf = 0; mf < 4; mf++)
#pragma unroll
        for (int h = 0; h < 2; h++) {
            float v = rs[mf][h];
            v += __shfl_xor_sync(0xFFFFFFFFu, v, 1);
            v += __shfl_xor_sync(0xFFFFFFFFu, v, 2);
            rs[mf][h] = v;
        }
    if (tg == 0) {
#pragma unroll
        for (int mf = 0; mf < 4; mf++) {
            int r = wm * 64 + mf * 16 + gid;
            // accumulate across wn via atomic-free: 4 slices
            red[(wn & 1) * 128 + r] = 0.f;  // init below instead
        }
    }
    __syncthreads();
    // simple: each wn writes its own slice of 128, then sum 4 slices? smem is 256 floats.
    // Use two-stage: wn pairs add via shfl across warps not possible -> use 4 slices in red of 512B?
    // red has 256 floats; reuse: slice = wn*... need 4*128 = 512 floats. Use sP-free space: put in SB0.
    {
        float* red4 = reinterpret_cast<float*>(sm + SB0);  // 512 floats, tiles dead now
        if (tg == 0) {
#pragma unroll
            for (int mf = 0; mf < 4; mf++) {
                int r = wm * 64 + mf * 16 + gid;
                red4[wn * 128 + r]     = rs[mf][0];
                red4[wn * 128 + r + 8] = rs[mf][1];
            }
        }
        __syncthreads();
        if (tid < 128) {
            float c = red4[tid] + red4[128 + tid] + red4[256 + tid] + red4[384 + tid];
            g_r[b * T_DIM + j0 + tid] = 1.0f / c;
        }
    }
}

// ---------------- k_out ----------------
// smem: sa0 @0 sr0 @512 sa1 @1024 sr1 @1536 | XI @2048 | XJ0 @20480 | XJ1 @38912 |
//       XJT0 @57344 | XJT1 @74752 | P @92160 | total 126976
__global__ void __launch_bounds__(256, 1) k_out(float* __restrict__ out) {
    extern __shared__ char sm[];
    const uint32_t smb = smem_u32(sm);
    const int tid = threadIdx.x, w = tid >> 5, lane = tid & 31;
    const int wm = w >> 2, wn = w & 3;
    const int gid = lane >> 2, tg = lane & 3;
    const int b = blockIdx.y, i0 = blockIdx.x * 128;
    const __half* xh  = g_xh  + (size_t)b * T_DIM * D_DIM;
    const __half* xth = g_xth + (size_t)b * D_DIM * T_DIM;
    float* ob = out + (size_t)b * D_DIM * T_DIM;

    const uint32_t XI = 2048, XJ0 = 20480, XJ1 = 38912, XJT0 = 57344, XJT1 = 74752, P = 92160;
    const __half* pXi = reinterpret_cast<const __half*>(sm + XI);
    __half* pP = reinterpret_cast<__half*>(sm + P);

    // prologue: Xi + tile 0
    ld_x(smb + XI, xh + (size_t)i0 * D_DIM, tid);
    ld_x(smb + XJ0, xh, tid);
    ld_xt(smb + XJT0, xth, tid);
    if (tid < 128) {
        reinterpret_cast<float*>(sm + 0)[tid]   = g_a[b * T_DIM + tid];
        reinterpret_cast<float*>(sm + 512)[tid] = g_r[b * T_DIM + tid];
    }
    CP_COMMIT();
    CP_WAIT0();
    __syncthreads();

    float accO[4][2][4];
#pragma unroll
    for (int mf = 0; mf < 4; mf++)
#pragma unroll
        for (int nf = 0; nf < 2; nf++)
#pragma unroll
            for (int q = 0; q < 4; q++) accO[mf][nf][q] = 0.f;

    for (int t = 0; t < NIT; t++) {
        const int buf = t & 1, nb = buf ^ 1;
        const uint32_t XJ  = buf ? XJ1 : XJ0;
        const uint32_t XJT = buf ? XJT1 : XJT0;
        const __half* pXj = reinterpret_cast<const __half*>(sm + XJ);
        const __half* pT  = reinterpret_cast<const __half*>(sm + XJT);
        const float* sa = reinterpret_cast<const float*>(sm + (uint32_t)buf * 1024);
        const float* sr = reinterpret_cast<const float*>(sm + (uint32_t)buf * 1024 + 512);

        if (t + 1 < NIT) {
            ld_x(smb + (nb ? XJ1 : XJ0), xh + (size_t)(t + 1) * NCH * D_DIM, tid);
            ld_xt(smb + (nb ? XJT1 : XJT0), xth + (size_t)(t + 1) * NCH, tid);
            CP_COMMIT();
            if (tid < 128) {
                reinterpret_cast<float*>(sm + (uint32_t)nb * 1024)[tid] =
                    g_a[b * T_DIM + (t + 1) * NCH + tid];
                reinterpret_cast<float*>(sm + (uint32_t)nb * 1024 + 512)[tid] =
                    g_r[b * T_DIM + (t + 1) * NCH + tid];
            }
        }

        // ---- S = Xi * Xj^T ----
        float accS[4][4][4];
#pragma unroll
        for (int mf = 0; mf < 4; mf++)
#pragma unroll
            for (int nf = 0; nf < 4; nf++)
#pragma unroll
                for (int q = 0; q < 4; q++) accS[mf][nf][q] = 0.f;

#pragma unroll
        for (int kk = 0; kk < 4; kk++) {
            const int k0 = kk * 16;
            uint32_t A[4][4], Bf[4][2];
#pragma unroll
            for (int mf = 0; mf < 4; mf++) {
                int r = wm * 64 + mf * 16 + gid;
                A[mf][0] = *reinterpret_cast<const uint32_t*>(pXi + r * LDX + k0 + 2 * tg);
                A[mf][1] = *reinterpret_cast<const uint32_t*>(pXi + (r + 8) * LDX + k0 + 2 * tg);
                A[mf][2] = *reinterpret_cast<const uint32_t*>(pXi + r * LDX + k0 + 8 + 2 * tg);
                A[mf][3] = *reinterpret_cast<const uint32_t*>(pXi + (r + 8) * LDX + k0 + 8 + 2 * tg);
            }
#pragma unroll
            for (int nf = 0; nf < 4; nf++) {
                int cB = wn * 32 + nf * 8 + gid;
                Bf[nf][0] = *reinterpret_cast<const uint32_t*>(pXj + cB * LDX + k0 + 2 * tg);
                Bf[nf][1] = *reinterpret_cast<const uint32_t*>(pXj + cB * LDX + k0 + 8 + 2 * tg);
            }
#pragma unroll
            for (int mf = 0; mf < 4; mf++)
#pragma unroll
                for (int nf = 0; nf < 4; nf++)
                    mma_f16(accS[mf][nf], A[mf], Bf[nf]);
        }

        // ---- P = exp(S - a_j) * r_j -> fp16 SMEM ----
#pragma unroll
        for (int nf = 0; nf < 4; nf++) {
            int c0 = wn * 32 + nf * 8 + 2 * tg;
            float a0 = sa[c0], a1 = sa[c0 + 1];
            float r0v = sr[c0], r1v = sr[c0 + 1];
#pragma unroll
            for (int mf = 0; mf < 4; mf++) {
                int r = wm * 64 + mf * 16 + gid;
                __half2 p01 = __floats2half2_rn(__expf(accS[mf][nf][0] - a0) * r0v,
                                                __expf(accS[mf][nf][1] - a1) * r1v);
                __half2 p23 = __floats2half2_rn(__expf(accS[mf][nf][2] - a0) * r0v,
                                                __expf(accS[mf][nf][3] - a1) * r1v);
                *reinterpret_cast<__half2*>(pP + r * LDT + c0)       = p01;
                *reinterpret_cast<__half2*>(pP + (r + 8) * LDT + c0) = p23;
            }
        }
        __syncthreads();  // sP visible to all warps

        // ---- O += P(128x128) * XjT ----
#pragma unroll
        for (int kk = 0; kk < 8; kk++) {
            const int k0 = kk * 16;
            uint32_t A[4][4], Bf[2][2];
#pragma unroll
            for (int mf = 0; mf < 4; mf++) {
                int r = wm * 64 + mf * 16 + gid;
                A[mf][0] = *reinterpret_cast<const uint32_t*>(pP + r * LDT + k0 + 2 * tg);
                A[mf][1] = *reinterpret_cast<const uint32_t*>(pP + (r + 8) * LDT + k0 + 2 * tg);
                A[mf][2] = *reinterpret_cast<const uint32_t*>(pP + r * LDT + k0 + 8 + 2 * tg);
                A[mf][3] = *reinterpret_cast<const uint32_t*>(pP + (r + 8) * LDT + k0 + 8 + 2 * tg);
            }
#pragma unroll
            for (int nf = 0; nf < 2; nf++) {
                int cB = wn * 16 + nf * 8 + gid;
                Bf[nf][0] = *reinterpret_cast<const uint32_t*>(pT + cB * LDT + k0 + 2 * tg);
                Bf[nf][1] = *reinterpret_cast<const uint32_t*>(pT + cB * LDT + k0 + 8 + 2 * tg);
            }
#pragma unroll
            for (int mf = 0; mf < 4; mf++)
#pragma unroll
                for (int nf = 0; nf < 2; nf++)
                    mma_f16(accO[mf][nf], A[mf], Bf[nf]);
        }

        if (t + 1 < NIT) CP_WAIT0();
        __syncthreads();
    }

    // ---- store transposed: out[b][d][i] ----
#pragma unroll
    for (int mf = 0; mf < 4; mf++)
#pragma unroll
        for (int nf = 0; nf < 2; nf++) {
            int r = i0 + wm * 64 + mf * 16 + gid;
            int c = wn * 16 + nf * 8 + 2 * tg;
            ob[(size_t)c * T_DIM + r]           = accO[mf][nf][0];
            ob[(size_t)(c + 1) * T_DIM + r]     = accO[mf][nf][1];
            ob[(size_t)c * T_DIM + r + 8]       = accO[mf][nf][2];
            ob[(size_t)(c + 1) * T_DIM + r + 8] = accO[mf][nf][3];
        }
}

// ---------------------------------------------------------------------------
extern "C" void kernel_launch(void* const* d_in, const int* in_sizes, int n_in,
                              void* d_out, int out_size) {
    const float* x = (const float*)d_in[0];
    float* out = (float*)d_out;

    const int smem_stats = 56320;
    const int smem_out   = 126976;
    cudaFuncSetAttribute(k_stats, cudaFuncAttributeMaxDynamicSharedMemorySize, smem_stats);
    cudaFuncSetAttribute(k_out,   cudaFuncAttributeMaxDynamicSharedMemorySize, smem_out);

    k_prep<<<(B_DIM * T_DIM) / 16, 256>>>(x);
    k_xt<<<dim3(T_DIM / 32, D_DIM / 32, B_DIM), 256>>>(x);
    k_stats<<<dim3(T_DIM / 128, B_DIM), 256, smem_stats>>>();
    k_out<<<dim3(T_DIM / 128, B_DIM), 256, smem_out>>>(out);
}